// round 3
// baseline (speedup 1.0000x reference)
#include <cuda_runtime.h>
#include <math.h>
#include <stdint.h>

#define B_ 32768
#define N_ 5
#define D_ 32
#define H_ 128
#define ROWS (B_*N_)          // 163840
#define BH (B_*H_)            // 4194304

static constexpr long long OFF_VAR = (long long)B_*N_*D_;      // 5242880
static constexpr long long OFF_GRU = 2LL*B_*N_*D_;             // 10485760
static constexpr long long OFF_TOT = OFF_GRU + 2LL*B_*H_;      // 18874368
static constexpr long long OFF_LS  = OFF_TOT + 1;

// ---------------- static scratch ----------------
__device__ float BA[ROWS*H_];
__device__ float BB[ROWS*H_];
__device__ float BC[ROWS*H_];
__device__ float BD[ROWS*H_];
__device__ float DEC[ROWS*64];
__device__ float GF[B_*H_];
__device__ float GI[B_*384];
__device__ float GH[B_*384];

// accumulators: 0 kl, 1 ll, 2 reg, 3 cls, 4 lz
__device__ double g_acc[8];
__device__ double g_piw[32], g_k[32];
__device__ unsigned g_mn[32], g_mx[32];

// ---------------- helpers ----------------
__device__ __forceinline__ float softplusf(float x){ return fmaxf(x,0.f)+log1pf(expf(-fabsf(x))); }
__device__ __forceinline__ float mishf(float x){ return x*tanhf(softplusf(x)); }
__device__ __forceinline__ float sigmf(float x){ return 1.f/(1.f+expf(-x)); }
__device__ __forceinline__ unsigned fenc(float f){ unsigned u=__float_as_uint(f); return (u&0x80000000u)?~u:(u|0x80000000u); }
__device__ __forceinline__ float fdec(unsigned u){ return (u&0x80000000u)?__uint_as_float(u&0x7fffffffu):__uint_as_float(~u); }

__global__ void init_k(){
    int i=threadIdx.x;
    if(i<8) g_acc[i]=0.0;
    if(i<32){ g_piw[i]=0.0; g_k[i]=0.0; g_mn[i]=0xffffffffu; g_mx[i]=0u; }
}

// ---------------- generic SGEMM ----------------
#define EPI_NONE 0
#define EPI_RELU 1
#define EPI_MISH 2
#define EPI_SIGKL 3
#define EPI_LZ 4

// C[row,col] = epi( sum_k A[row,k]*B[k,col] + bias[col] )
// TRB: B[k,col] = Bw[col*ldb + k]   (for GRU W^T)
// blockIdx.z selects per-n slice via *zs element offsets.
template<int BN, int TM, int EPI, bool TRB>
__global__ __launch_bounds__(256)
void gemm_k(const float* __restrict__ A, int lda, int azs,
            const float* __restrict__ Bw, int ldb, int bzs,
            const float* __restrict__ bias, int biaszs,
            float* __restrict__ C, int ldc, int czs,
            const float* __restrict__ aux,
            int K)
{
    constexpr int BM=64, TN=4;
    constexpr int RT=BM/TM;
    __shared__ float As[BM][17];
    __shared__ float Bs[16][BN+4];
    __shared__ double red[256];

    int tid=threadIdx.x;
    int z = blockIdx.z;
    A    += (size_t)z*azs;
    Bw   += (size_t)z*bzs;
    bias += (size_t)z*biaszs;
    if (C)   C   += (size_t)z*czs;
    if (aux) aux += (size_t)z*czs;

    int row0 = blockIdx.y*BM;
    int col0 = blockIdx.x*BN;
    int r = tid % RT, c = tid / RT;

    float acc[TM][TN];
    #pragma unroll
    for(int i=0;i<TM;i++){
        #pragma unroll
        for(int j=0;j<TN;j++) acc[i][j]=0.f;
    }

    for (int k0=0;k0<K;k0+=16){
        {   // A tile: 64x16, one float4 per thread
            int ar = tid>>2, kq=(tid&3)*4;
            float4 av = *reinterpret_cast<const float4*>(&A[(size_t)(row0+ar)*lda + k0 + kq]);
            As[ar][kq]=av.x; As[ar][kq+1]=av.y; As[ar][kq+2]=av.z; As[ar][kq+3]=av.w;
        }
        #pragma unroll
        for (int p=0;p<(16*BN)/256;p++){
            int id = tid + p*256;
            if (!TRB){ int k=id/BN, j=id%BN; Bs[k][j]=Bw[(size_t)(k0+k)*ldb + col0 + j]; }
            else     { int k=id&15,  j=id>>4; Bs[k][j]=Bw[(size_t)(col0+j)*ldb + k0 + k]; }
        }
        __syncthreads();
        #pragma unroll
        for (int kk=0;kk<16;kk++){
            float a[TM];
            #pragma unroll
            for(int i=0;i<TM;i++) a[i]=As[r*TM+i][kk];
            float4 bv = *reinterpret_cast<const float4*>(&Bs[kk][c*TN]);
            #pragma unroll
            for(int i=0;i<TM;i++){
                acc[i][0]=fmaf(a[i],bv.x,acc[i][0]);
                acc[i][1]=fmaf(a[i],bv.y,acc[i][1]);
                acc[i][2]=fmaf(a[i],bv.z,acc[i][2]);
                acc[i][3]=fmaf(a[i],bv.w,acc[i][3]);
            }
        }
        __syncthreads();
    }

    int col = col0 + c*TN;
    float4 bb = *reinterpret_cast<const float4*>(&bias[col]);
    float bArr[4]={bb.x,bb.y,bb.z,bb.w};
    double part=0.0;
    #pragma unroll
    for(int i=0;i<TM;i++){
        int row = row0 + r*TM + i;
        float v[4];
        #pragma unroll
        for(int j=0;j<4;j++){
            float x = acc[i][j]+bArr[j];
            if (EPI==EPI_RELU) x = fmaxf(x,0.f);
            else if (EPI==EPI_MISH) x = mishf(x);
            else if (EPI==EPI_SIGKL){
                float sp = softplusf(x);
                float var = sp*sp;
                float m = aux[(size_t)row*ldc + col + j];
                part += (double)(0.5f*(m*m + var - logf(var+1e-8f) - 1.0f));
            }
            else if (EPI==EPI_LZ){
                float d = aux[(size_t)row*ldc + col + j] - x;
                part += (double)(d*d);
            }
            v[j]=x;
        }
        if (EPI<=EPI_MISH){
            float4 o; o.x=v[0]; o.y=v[1]; o.z=v[2]; o.w=v[3];
            *reinterpret_cast<float4*>(&C[(size_t)row*ldc + col]) = o;
        }
    }
    if (EPI>=EPI_SIGKL){
        red[tid]=part; __syncthreads();
        for(int s=128;s>0;s>>=1){ if(tid<s) red[tid]+=red[tid+s]; __syncthreads(); }
        if(tid==0) atomicAdd(&g_acc[EPI==EPI_SIGKL?0:4], red[0]);
    }
}

// ---------------- elementwise kernels ----------------
// agg[b,v,h] = g[b,v,h] + sum_{e:dst=v} ew[b,e]*g[b,src_e,h]
// edges (triu k=1): (0,1)(0,2)(0,3)(0,4)(1,2)(1,3)(1,4)(2,3)(2,4)(3,4)
__global__ void agg_k(const float* __restrict__ g, const float* __restrict__ ew, float* __restrict__ o){
    int idx = blockIdx.x*256+threadIdx.x;
    int b=idx>>7, h=idx&127;
    const float* gb = g + (size_t)b*640 + h;
    float g0=gb[0],g1=gb[128],g2=gb[256],g3=gb[384],g4=gb[512];
    const float* e = ew + (size_t)b*10;
    float e0=e[0],e1=e[1],e2=e[2],e3=e[3],e4=e[4],e5=e[5],e6=e[6],e7=e[7],e8=e[8],e9=e[9];
    float* ob = o + (size_t)b*640 + h;
    ob[0]  = g0;
    ob[128]= g1 + e0*g0;
    ob[256]= g2 + e1*g0 + e4*g1;
    ob[384]= g3 + e2*g0 + e5*g1 + e7*g2;
    ob[512]= g4 + e3*g0 + e6*g1 + e8*g2 + e9*g3;
}

__global__ void gf_k(const float* __restrict__ m, float* __restrict__ gf){
    int idx = blockIdx.x*256+threadIdx.x;
    int b=idx>>7, h=idx&127;
    const float* mb = m + (size_t)b*640 + h;
    gf[idx] = (mb[0]+mb[128]+mb[256]+mb[384]+mb[512])*0.2f;
}

__global__ void cell_k(const float* __restrict__ gi, const float* __restrict__ gh,
                       const float* __restrict__ hprev, float* __restrict__ hout){
    int idx = blockIdx.x*256+threadIdx.x;
    int b=idx>>7, h=idx&127;
    int base = b*384 + h;
    float r = sigmf(gi[base]     + gh[base]);
    float z = sigmf(gi[base+128] + gh[base+128]);
    float n = tanhf(gi[base+256] + r*gh[base+256]);
    hout[idx] = (1.f-z)*n + z*hprev[idx];
}

// forward substitution (I - ac^T) z = m, plus parent_sum
__global__ void causal_k(const float* __restrict__ m, const float* __restrict__ ew,
                         const float* __restrict__ cm, float* __restrict__ cz, float* __restrict__ ps){
    int idx = blockIdx.x*256+threadIdx.x;
    int b=idx>>7, h=idx&127;
    const float* mb = m + (size_t)b*640 + h;
    const float* e  = ew + (size_t)b*10;
    float c01=cm[1]*e[0],  c02=cm[2]*e[1],  c03=cm[3]*e[2],  c04=cm[4]*e[3];
    float c12=cm[7]*e[4],  c13=cm[8]*e[5],  c14=cm[9]*e[6];
    float c23=cm[13]*e[7], c24=cm[14]*e[8];
    float c34=cm[19]*e[9];
    float z0=mb[0];
    float z1=mb[128]+c01*z0;
    float z2=mb[256]+c02*z0+c12*z1;
    float z3=mb[384]+c03*z0+c13*z1+c23*z2;
    float z4=mb[512]+c04*z0+c14*z1+c24*z2+c34*z3;
    float* czb = cz + (size_t)b*640 + h;
    czb[0]=z0; czb[128]=z1; czb[256]=z2; czb[384]=z3; czb[512]=z4;
    float zv[5]={z0,z1,z2,z3,z4};
    float* psb = ps + (size_t)b*640 + h;
    #pragma unroll
    for(int j=0;j<5;j++){
        float s=0.f;
        #pragma unroll
        for(int i=0;i<5;i++){
            if (cm[i*5+j]!=0.f) s += zv[i];
        }
        psb[j*128]=s;
    }
}

// ---------------- final per-element losses ----------------
__global__ __launch_bounds__(256)
void loss_k(const float* __restrict__ dec, const float* __restrict__ ytp, float* __restrict__ out){
    int warp = threadIdx.x>>5, lane = threadIdx.x&31;
    int base = blockIdx.x*128;
    const float ZA = 1.959963984540054f;
    double ll_s=0.0, piw_s=0.0;
    float reg_s=0.f, cls_s=0.f;
    int k_s=0;
    float mn=3e38f, mx=-3e38f;
    for(int t=0;t<16;t++){
        int row = base + warp*16 + t;
        int n = row % 5;
        const float* dr = dec + (size_t)row*64;
        float mean = dr[lane];
        float var  = expf(dr[32+lane]);
        size_t oi = (size_t)row*32 + lane;
        out[oi]=mean; out[OFF_VAR+oi]=var;
        float yt = ytp[oi];
        float vs = var+1e-6f;
        float dm = yt-mean;
        ll_s += (double)(-0.5f*(dm*dm/vs + logf(6.283185307179586f*vs)));
        float d2 = dm*dm;
        float ssum=d2;
        #pragma unroll
        for(int o=16;o;o>>=1) ssum += __shfl_xor_sync(0xffffffffu,ssum,o);
        if (lane==0 && n<4) reg_s += ssum*(1.f/32.f);
        if (n==4){
            float bce = fmaxf(mean,0.f)-mean*yt+log1pf(expf(-fabsf(mean)));
            float bs=bce;
            #pragma unroll
            for(int o=16;o;o>>=1) bs += __shfl_xor_sync(0xffffffffu,bs,o);
            if (lane==0) cls_s += bs*(1.f/32.f);
        }
        float s = sqrtf(var+1e-6f);
        float lo = mean-ZA*s, up = mean+ZA*s;
        if (yt>=lo && yt<=up){ piw_s += (double)(up-lo); k_s++; }
        mn=fminf(mn,yt); mx=fmaxf(mx,yt);
    }
    #pragma unroll
    for(int o=16;o;o>>=1) ll_s += __shfl_xor_sync(0xffffffffu,ll_s,o);

    __shared__ double sll[8];
    __shared__ float sreg[8], scls[8];
    __shared__ float spiw[8][32], sk[8][32];
    __shared__ unsigned smn[8][32], smx[8][32];
    if (lane==0){ sll[warp]=ll_s; sreg[warp]=reg_s; scls[warp]=cls_s; }
    spiw[warp][lane]=(float)piw_s; sk[warp][lane]=(float)k_s;
    smn[warp][lane]=fenc(mn); smx[warp][lane]=fenc(mx);
    __syncthreads();
    if (warp==0){
        double psum=0, ksum=0; unsigned mnu=0xffffffffu, mxu=0u;
        for(int w=0;w<8;w++){
            psum+=(double)spiw[w][lane]; ksum+=(double)sk[w][lane];
            mnu=min(mnu,smn[w][lane]); mxu=max(mxu,smx[w][lane]);
        }
        atomicAdd(&g_piw[lane],psum); atomicAdd(&g_k[lane],ksum);
        atomicMin(&g_mn[lane],mnu);   atomicMax(&g_mx[lane],mxu);
        if (lane==0){
            double L=0; float R=0,Cc=0;
            for(int w=0;w<8;w++){ L+=sll[w]; R+=sreg[w]; Cc+=scls[w]; }
            atomicAdd(&g_acc[1],L); atomicAdd(&g_acc[2],(double)R); atomicAdd(&g_acc[3],(double)Cc);
        }
    }
}

__global__ void fin_k(float* __restrict__ out){
    int lane=threadIdx.x;
    double t=0.0, kc=0.0;
    double p=g_piw[lane]; kc=g_k[lane];
    float ymn=fdec(g_mn[lane]), ymx=fdec(g_mx[lane]);
    t = p/(kc+1e-6)/((double)(ymx-ymn)+1e-6);
    #pragma unroll
    for(int o=16;o;o>>=1){
        t  += __shfl_xor_sync(0xffffffffu,t,o);
        kc += __shfl_xor_sync(0xffffffffu,kc,o);
    }
    if (lane==0){
        float pinaw=(float)(t/32.0);
        float picp =(float)(kc/5242880.0);
        float kl   =(float)g_acc[0];
        float elbo = kl/32768.0f - (float)(g_acc[1]/5242880.0);
        float l_reg=(float)(g_acc[2]/(4.0*32768.0+1e-6));
        float l_cls=(float)(g_acc[3]/(32768.0+1e-6));
        float l_rec=l_reg+l_cls;
        float l_pi = pinaw - sqrtf(5.f)*picp;
        float l_z  =(float)(g_acc[4]/(163840.0*128.0));
        float dag  = 0.f;  // trace((I+ac)^5) == N exactly (strictly upper triangular)
        float total= powf(elbo*l_rec*l_pi*l_z*(dag+1e-6f), 0.2f);
        out[OFF_TOT]=total;
        out[OFF_LS+0]=elbo; out[OFF_LS+1]=l_rec; out[OFF_LS+2]=l_pi;
        out[OFF_LS+3]=l_z;  out[OFF_LS+4]=dag;
    }
}

// ---------------- launcher ----------------
extern "C" void kernel_launch(void* const* d_in, const int* in_sizes, int n_in,
                              void* d_out, int out_size)
{
    const float* x    =(const float*)d_in[0];
    const float* ytr  =(const float*)d_in[1];
    const float* ew   =(const float*)d_in[2];
    const float* hist =(const float*)d_in[3];
    const float* eW1  =(const float*)d_in[4];
    const float* eb1  =(const float*)d_in[5];
    const float* eW2  =(const float*)d_in[6];
    const float* eb2  =(const float*)d_in[7];
    const float* gW   =(const float*)d_in[8];
    const float* gb   =(const float*)d_in[9];
    const float* muW  =(const float*)d_in[10];
    const float* mub  =(const float*)d_in[11];
    const float* sgW  =(const float*)d_in[12];
    const float* sgb  =(const float*)d_in[13];
    const float* Wih  =(const float*)d_in[14];
    const float* Whh  =(const float*)d_in[15];
    const float* bih  =(const float*)d_in[16];
    const float* bhh  =(const float*)d_in[17];
    const float* cm   =(const float*)d_in[18];
    const float* cW1  =(const float*)d_in[19];
    const float* cb1  =(const float*)d_in[20];
    const float* cW2  =(const float*)d_in[21];
    const float* cb2  =(const float*)d_in[22];
    const float* dW1  =(const float*)d_in[23];
    const float* db1  =(const float*)d_in[24];
    const float* dW2  =(const float*)d_in[25];
    const float* db2  =(const float*)d_in[26];
    float* out=(float*)d_out;

    float *pBA,*pBB,*pBC,*pBD,*pDEC,*pGF,*pGI,*pGH;
    cudaGetSymbolAddress((void**)&pBA,BA);
    cudaGetSymbolAddress((void**)&pBB,BB);
    cudaGetSymbolAddress((void**)&pBC,BC);
    cudaGetSymbolAddress((void**)&pBD,BD);
    cudaGetSymbolAddress((void**)&pDEC,DEC);
    cudaGetSymbolAddress((void**)&pGF,GF);
    cudaGetSymbolAddress((void**)&pGI,GI);
    cudaGetSymbolAddress((void**)&pGH,GH);

    init_k<<<1,64>>>();

    // encoder: h1 = relu(x @ W1[n] + b1[n]) ; h = h1 @ W2[n] + b2[n]
    gemm_k<128,8,EPI_RELU,false><<<dim3(1,512,5),256>>>(x,160,32,   eW1,128,4096,  eb1,128, pBA,640,128, nullptr, 32);
    gemm_k<128,8,EPI_NONE,false><<<dim3(1,512,5),256>>>(pBA,640,128, eW2,128,16384, eb2,128, pBB,640,128, nullptr, 128);

    // GCN x2
    agg_k<<<16384,256>>>(pBB,ew,pBC);
    gemm_k<128,8,EPI_RELU,false><<<dim3(1,2560,1),256>>>(pBC,128,0, gW,128,0,        gb,0,     pBA,128,0, nullptr, 128);
    agg_k<<<16384,256>>>(pBA,ew,pBC);
    gemm_k<128,8,EPI_RELU,false><<<dim3(1,2560,1),256>>>(pBC,128,0, gW+16384,128,0,  gb+128,0, pBB,128,0, nullptr, 128);

    // mu / sigma (+KL accumulation)
    gemm_k<128,8,EPI_NONE,false><<<dim3(1,2560,1),256>>>(pBB,128,0, muW,128,0, mub,0, pBD,128,0, nullptr, 128);
    gemm_k<128,8,EPI_SIGKL,false><<<dim3(1,2560,1),256>>>(pBB,128,0, sgW,128,0, sgb,0, nullptr,128,0, pBD, 128);

    gf_k<<<16384,256>>>(pBD,pGF);

    // GRU x2 (W^T GEMMs)
    const float* gin = pGF;
    for (int l=0;l<2;l++){
        gemm_k<128,8,EPI_NONE,true><<<dim3(3,512,1),256>>>(gin,128,0,              Wih+(size_t)l*49152,128,0, bih+l*384,0, pGI,384,0, nullptr, 128);
        gemm_k<128,8,EPI_NONE,true><<<dim3(3,512,1),256>>>(hist+(size_t)l*BH,128,0, Whh+(size_t)l*49152,128,0, bhh+l*384,0, pGH,384,0, nullptr, 128);
        cell_k<<<16384,256>>>(pGI,pGH, hist+(size_t)l*BH, out+OFF_GRU+(size_t)l*BH);
        gin = out+OFF_GRU+(size_t)l*BH;
    }

    // causal solve + parent_sum; cm MLP (+l_z accumulation)
    causal_k<<<16384,256>>>(pBD, ew, cm, pBA, pBC);
    gemm_k<128,8,EPI_MISH,false><<<dim3(1,2560,1),256>>>(pBC,128,0, cW1,128,0, cb1,0, pBB,128,0, nullptr, 128);
    gemm_k<128,8,EPI_LZ,false><<<dim3(1,2560,1),256>>>(pBB,128,0, cW2,128,0, cb2,0, nullptr,128,0, pBA, 128);

    // decoder
    gemm_k<128,8,EPI_MISH,false><<<dim3(1,512,5),256>>>(pBA,640,128, dW1,128,16384, db1,128, pBC,640,128, nullptr, 128);
    gemm_k<64,4,EPI_NONE,false><<<dim3(1,512,5),256>>>(pBC,640,128, dW2,64,8192,   db2,64,  pDEC,320,64, nullptr, 128);

    // losses
    loss_k<<<1280,256>>>(pDEC, ytr, out);
    fin_k<<<1,32>>>(out);
}